// round 14
// baseline (speedup 1.0000x reference)
#include <cuda_runtime.h>
#include <cuda_fp16.h>
#include <cstdint>

#define B_    16
#define N_    4096
#define D_    64
#define NCOL  1024

// ---- stage-2 GEMM tiling (fp16 operands, fp32 accum) ----
#define MT      128          // CTA M tile
#define NTI     256          // CTA N tile
#define KT      64           // K chunk (4 x k16 steps)
#define STAGES  4
#define NCHUNK  (N_ / KT)    // 64
#define NTHR    512          // 16 warps: 2 (m) x 8 (n), warp tile 64x32

#define A_U4      1024                   // uint4 of A per stage (16 KB)
#define B_U4      2048                   // uint4 of B per stage (32 KB)
#define STAGE_U4  (A_U4 + B_U4)          // 3072 (48 KB)
#define SMEM_BYTES (STAGES * STAGE_U4 * 16)   // 196608

// ---- scratch (device globals) ----
// g_Ah: A in fp16, fragment order for mma.m16n8k16 (MT=128):
//   [mtile 32][kc 64][mb 8][k16 4][lane 32] x uint4 (regs a0..a3)
//   a0=(r0,c0:c0+1) a1=(r0+8,c0:c0+1) a2=(r0,c0+8:+9) a3=(r0+8,c0+8:+9)
//   r0 = mtile*128+mb*16+(lane>>2), c0 = kc*64+k16*16+(lane&3)*2
__device__ uint4 g_Ah[(size_t)32 * 64 * 8 * 4 * 32];          // 32 MB
// g_Xb: X in B-fragment order (NTI=256):
//   [ntile 4][kc 64][nb 32][k16 4][lane 32] x uint2 (regs b0,b1)
//   b0=(k0+2tg, k0+2tg+1 ; n)  b1=(+8,+9 ; n)
//   n = ntile*256+nb*8+(lane>>2), k0 = kc*64+k16*16
__device__ uint2 g_Xb[(size_t)4 * 64 * 32 * 4 * 32];          // 8 MB

// ---------------------------------------------------------------------------
__device__ __forceinline__ void cp_async16(void* smem_dst, const void* gmem_src) {
    uint32_t a;
    asm("{ .reg .u64 t; cvta.to.shared.u64 t, %1; cvt.u32.u64 %0, t; }"
        : "=r"(a) : "l"(smem_dst));
    asm volatile("cp.async.cg.shared.global [%0], [%1], 16;"
                 :: "r"(a), "l"(gmem_src) : "memory");
}
#define CP_COMMIT() asm volatile("cp.async.commit_group;" ::: "memory")
#define CP_WAIT2()  asm volatile("cp.async.wait_group 2;" ::: "memory")

__device__ __forceinline__ void mma_f16(float c[4], const uint32_t a[4],
                                        const uint32_t b[2]) {
    asm volatile(
        "mma.sync.aligned.m16n8k16.row.col.f32.f16.f16.f32 "
        "{%0,%1,%2,%3}, {%4,%5,%6,%7}, {%8,%9}, {%0,%1,%2,%3};"
        : "+f"(c[0]), "+f"(c[1]), "+f"(c[2]), "+f"(c[3])
        : "r"(a[0]), "r"(a[1]), "r"(a[2]), "r"(a[3]), "r"(b[0]), "r"(b[1]));
}

__device__ __forceinline__ uint32_t pack_h2(float lo, float hi) {
    const __half2 h = __floats2half2_rn(lo, hi);   // lo -> low 16 bits
    return *reinterpret_cast<const uint32_t*>(&h);
}

// ---------------------------------------------------------------------------
// Prep A: g_Ah = fragment-ordered fp16(A). One uint4 per thread.
// ---------------------------------------------------------------------------
__global__ __launch_bounds__(256) void aprep_kernel(const float* __restrict__ A) {
    const uint32_t idx = blockIdx.x * 256 + threadIdx.x;   // 0 .. 2097151
    const int lane  = idx & 31;
    const int k16   = (idx >> 5) & 3;
    const int mb    = (idx >> 7) & 7;
    const int kc    = (idx >> 10) & 63;
    const int mtile = idx >> 16;
    const int g = lane >> 2, tg = lane & 3;

    const int r0 = mtile * 128 + mb * 16 + g;
    const int c0 = kc * 64 + k16 * 16 + tg * 2;
    const float* p = A + (size_t)r0 * N_ + c0;

    const float2 v0 = *reinterpret_cast<const float2*>(p);
    const float2 v1 = *reinterpret_cast<const float2*>(p + 8 * N_);
    const float2 v2 = *reinterpret_cast<const float2*>(p + 8);
    const float2 v3 = *reinterpret_cast<const float2*>(p + 8 * N_ + 8);

    uint4 t;
    t.x = pack_h2(v0.x, v0.y);
    t.y = pack_h2(v1.x, v1.y);
    t.z = pack_h2(v2.x, v2.y);
    t.w = pack_h2(v3.x, v3.y);
    g_Ah[idx] = t;
}

// ---------------------------------------------------------------------------
// Stage 1 (fused): X tile = Z@W (exact fp32), then write B-fragments directly.
// Block (blockIdx.x = kc, blockIdx.y = b) covers exactly one fragment region.
// ---------------------------------------------------------------------------
__global__ __launch_bounds__(256) void zw_kernel(const float* __restrict__ Z,
                                                 const float* __restrict__ W) {
    __shared__ float sW[D_ * D_];
    __shared__ float sZ[64][65];
    __shared__ __half sXT[64][72];   // [n_local][m_local], pad 72 -> conflict-free
    const int tid = threadIdx.x;
    const int b = blockIdx.y;
    const int kc = blockIdx.x;
    const int m0 = kc * 64;

    for (int i = tid; i < D_ * D_; i += 256) sW[i] = W[i];
    const float4* Zp = reinterpret_cast<const float4*>(Z + ((size_t)b * N_ + m0) * D_);
    for (int f = tid; f < 1024; f += 256) {
        float4 v = Zp[f];
        int r = f >> 4, c = (f & 15) * 4;
        sZ[r][c] = v.x; sZ[r][c + 1] = v.y; sZ[r][c + 2] = v.z; sZ[r][c + 3] = v.w;
    }
    __syncthreads();

    const int tx = tid & 15, ty = tid >> 4;
    float acc[4][4] = {};
    #pragma unroll
    for (int d = 0; d < D_; d++) {
        const float4 w = *reinterpret_cast<const float4*>(&sW[d * D_ + tx * 4]);
        #pragma unroll
        for (int i = 0; i < 4; i++) {
            const float z = sZ[ty * 4 + i][d];
            acc[i][0] += z * w.x; acc[i][1] += z * w.y;
            acc[i][2] += z * w.z; acc[i][3] += z * w.w;
        }
    }
    #pragma unroll
    for (int j = 0; j < 4; j++) {
        const uint32_t h0 = pack_h2(acc[0][j], acc[1][j]);
        const uint32_t h1 = pack_h2(acc[2][j], acc[3][j]);
        *reinterpret_cast<uint32_t*>(&sXT[tx * 4 + j][ty * 4])     = h0;
        *reinterpret_cast<uint32_t*>(&sXT[tx * 4 + j][ty * 4 + 2]) = h1;
    }
    __syncthreads();

    const size_t base = (((size_t)(b >> 2) * 64 + kc) * 32 + (b & 3) * 8) * 128;
    #pragma unroll
    for (int it = 0; it < 4; it++) {
        const int f = tid + it * 256;              // nbl*128 + k16*32 + lane
        const int lane = f & 31;
        const int k16 = (f >> 5) & 3;
        const int nbl = f >> 7;
        const int n_local = nbl * 8 + (lane >> 2);
        const int k_local = k16 * 16 + (lane & 3) * 2;
        uint2 t;
        t.x = *reinterpret_cast<const uint32_t*>(&sXT[n_local][k_local]);
        t.y = *reinterpret_cast<const uint32_t*>(&sXT[n_local][k_local + 8]);
        g_Xb[base + f] = t;
    }
}

// ---------------------------------------------------------------------------
// Stage 2: Y = A @ X via mma.sync fp16/f32. CTA 128x256, 16 warps (2m x 8n),
// warp tile 64x32, K-chunk 64, 4-stage cp.async pipeline, fragment smem.
// ---------------------------------------------------------------------------
__global__ __launch_bounds__(NTHR, 1)
void gemm_mma_kernel(float* __restrict__ out) {
    extern __shared__ __align__(16) uint4 smem[];
    const int tid = threadIdx.x;
    const int ntile = blockIdx.x;   // 0..3
    const int mtile = blockIdx.y;   // 0..31

    const uint4* Abase = g_Ah + (size_t)mtile * 64 * A_U4;              // [kc][1024 u4]
    const uint4* Bbase = reinterpret_cast<const uint4*>(g_Xb)
                       + (size_t)ntile * 64 * B_U4;                     // [kc][2048 u4]

    auto load_stage = [&](int s, int i) {
        uint4* As4 = smem + s * STAGE_U4;
        uint4* Bs4 = As4 + A_U4;
        const uint4* Ag = Abase + (size_t)i * A_U4;
        const uint4* Bg = Bbase + (size_t)i * B_U4;
        #pragma unroll
        for (int j = 0; j < 2; j++) cp_async16(As4 + tid + j * NTHR, Ag + tid + j * NTHR);
        #pragma unroll
        for (int j = 0; j < 4; j++) cp_async16(Bs4 + tid + j * NTHR, Bg + tid + j * NTHR);
    };

    const int wid = tid >> 5;
    const int lane = tid & 31;
    const int g = lane >> 2;
    const int tg = lane & 3;
    const int mbw = (wid >> 3) * 4;      // warp m-row (0 or 1) -> mb base 0/4
    const int nbw = (wid & 7) * 4;       // warp n-col (0..7)   -> nb base 0..28

    float C[4][4][4] = {};               // [mt][nt][reg] — 64 regs

    load_stage(0, 0); CP_COMMIT();
    load_stage(1, 1); CP_COMMIT();
    load_stage(2, 2); CP_COMMIT();

    for (int i = 0; i < NCHUNK; i++) {
        CP_WAIT2();
        __syncthreads();

        if (i + 3 < NCHUNK) load_stage((i + 3) % STAGES, i + 3);
        CP_COMMIT();

        const int s = i % STAGES;
        const uint4* As4 = smem + s * STAGE_U4;
        const uint2* Bs2 = reinterpret_cast<const uint2*>(As4 + A_U4);

        #pragma unroll
        for (int kk = 0; kk < 4; kk++) {
            uint32_t a[4][4];
            #pragma unroll
            for (int mt = 0; mt < 4; mt++) {
                const uint4 av = As4[((mbw + mt) * 4 + kk) * 32 + lane];
                a[mt][0] = av.x; a[mt][1] = av.y; a[mt][2] = av.z; a[mt][3] = av.w;
            }
            uint32_t b[4][2];
            #pragma unroll
            for (int nt = 0; nt < 4; nt++) {
                const uint2 bv = Bs2[((nbw + nt) * 4 + kk) * 32 + lane];
                b[nt][0] = bv.x; b[nt][1] = bv.y;
            }
            #pragma unroll
            for (int mt = 0; mt < 4; mt++)
                #pragma unroll
                for (int nt = 0; nt < 4; nt++)
                    mma_f16(C[mt][nt], a[mt], b[nt]);
        }
        // next iteration's post-WAIT barrier orders compute(i) before load(i+4)
    }

    // ---- epilogue: scatter C to out[b][n][e] ----
    #pragma unroll
    for (int mt = 0; mt < 4; mt++) {
        const int row0 = mtile * MT + (mbw + mt) * 16 + g;
        #pragma unroll
        for (int nt = 0; nt < 4; nt++) {
            const int col = ntile * NTI + (nbw + nt) * 8 + tg * 2;  // even
            const int bb = col >> 6;
            const int e = col & 63;
            float* p = out + ((size_t)bb * N_ + row0) * D_ + e;
            *reinterpret_cast<float2*>(p) = make_float2(C[mt][nt][0], C[mt][nt][1]);
            *reinterpret_cast<float2*>(p + 8 * D_) = make_float2(C[mt][nt][2], C[mt][nt][3]);
        }
    }
}

// ---------------------------------------------------------------------------
extern "C" void kernel_launch(void* const* d_in, const int* in_sizes, int n_in,
                              void* d_out, int out_size) {
    const float* Z = (const float*)d_in[0];   // [16, 4096, 64]
    const float* A = (const float*)d_in[1];   // [4096, 4096]
    const float* W = (const float*)d_in[2];   // [64, 64]
    float* out = (float*)d_out;               // [16, 4096, 64]

    aprep_kernel<<<2097152 / 256, 256>>>(A);
    zw_kernel<<<dim3(N_ / 64, B_), 256>>>(Z, W);

    cudaFuncSetAttribute(gemm_mma_kernel,
                         cudaFuncAttributeMaxDynamicSharedMemorySize, SMEM_BYTES);
    gemm_mma_kernel<<<dim3(NCOL / NTI, N_ / MT), NTHR, SMEM_BYTES>>>(out);
}

// round 15
// speedup vs baseline: 1.0259x; 1.0259x over previous
#include <cuda_runtime.h>
#include <cuda_fp16.h>
#include <cstdint>

#define B_    16
#define N_    4096
#define D_    64
#define NCOL  1024

// ---- stage-2 GEMM tiling (fp16 operands, fp32 accum) ----
#define MT      128          // CTA M tile
#define NTI     128          // CTA N tile
#define KT      64           // K chunk (4 x k16 steps)
#define STAGES  3
#define NCHUNK  (N_ / KT)    // 64
#define NTHR    128          // 4 warps: 2 (m) x 2 (n), warp tile 64x64

#define A_U4      1024                   // uint4 of A per stage (16 KB)
#define B_U4      1024                   // uint4 of B per stage (16 KB)
#define STAGE_U4  (A_U4 + B_U4)          // 2048 (32 KB)
#define SMEM_BYTES (STAGES * STAGE_U4 * 16)   // 98304 -> 2 CTAs/SM

// ---- scratch (device globals) ----
// g_Ah: A in fp16, fragment order for mma.m16n8k16 (MT=128):
//   [mtile 32][kc 64][mb 8][k16 4][lane 32] x uint4 (regs a0..a3)
//   a0=(r0,c0:c0+1) a1=(r0+8,c0:c0+1) a2=(r0,c0+8:+9) a3=(r0+8,c0+8:+9)
//   r0 = mtile*128+mb*16+(lane>>2), c0 = kc*64+k16*16+(lane&3)*2
__device__ uint4 g_Ah[(size_t)32 * 64 * 8 * 4 * 32];          // 32 MB
// g_Xb: X in B-fragment order (NTI=128):
//   [ntile 8][kc 64][nb 16][k16 4][lane 32] x uint2 (regs b0,b1)
//   b0=(k0+2tg, k0+2tg+1 ; n)  b1=(+8,+9 ; n)
//   n = ntile*128+nb*8+(lane>>2), k0 = kc*64+k16*16
__device__ uint2 g_Xb[(size_t)8 * 64 * 16 * 4 * 32];          // 8 MB

// ---------------------------------------------------------------------------
__device__ __forceinline__ void cp_async16(void* smem_dst, const void* gmem_src) {
    uint32_t a;
    asm("{ .reg .u64 t; cvta.to.shared.u64 t, %1; cvt.u32.u64 %0, t; }"
        : "=r"(a) : "l"(smem_dst));
    asm volatile("cp.async.cg.shared.global [%0], [%1], 16;"
                 :: "r"(a), "l"(gmem_src) : "memory");
}
#define CP_COMMIT() asm volatile("cp.async.commit_group;" ::: "memory")
#define CP_WAIT1()  asm volatile("cp.async.wait_group 1;" ::: "memory")

__device__ __forceinline__ void mma_f16(float c[4], const uint32_t a[4],
                                        const uint32_t b[2]) {
    asm volatile(
        "mma.sync.aligned.m16n8k16.row.col.f32.f16.f16.f32 "
        "{%0,%1,%2,%3}, {%4,%5,%6,%7}, {%8,%9}, {%0,%1,%2,%3};"
        : "+f"(c[0]), "+f"(c[1]), "+f"(c[2]), "+f"(c[3])
        : "r"(a[0]), "r"(a[1]), "r"(a[2]), "r"(a[3]), "r"(b[0]), "r"(b[1]));
}

__device__ __forceinline__ uint32_t pack_h2(float lo, float hi) {
    const __half2 h = __floats2half2_rn(lo, hi);   // lo -> low 16 bits
    return *reinterpret_cast<const uint32_t*>(&h);
}

// ---------------------------------------------------------------------------
// Fused prep: blocks [0, 8192) convert A to fragment order (g_Ah);
// blocks [8192, 9216) compute X = Z@W (exact fp32) and write B-fragments.
// Independent work co-scheduled in one launch to overlap DRAM and FMA phases.
// ---------------------------------------------------------------------------
__global__ __launch_bounds__(256) void prep_kernel(const float* __restrict__ Z,
                                                   const float* __restrict__ A,
                                                   const float* __restrict__ W) {
    __shared__ float sW[D_ * D_];
    __shared__ float sZ[64][65];
    __shared__ __half sXT[64][72];   // [n_local][m_local], pad 72 -> conflict-free

    const int tid = threadIdx.x;

    if (blockIdx.x < 8192) {
        // ---------------- A prep ----------------
        const uint32_t idx = blockIdx.x * 256 + tid;       // 0 .. 2097151
        const int lane  = idx & 31;
        const int k16   = (idx >> 5) & 3;
        const int mb    = (idx >> 7) & 7;
        const int kc    = (idx >> 10) & 63;
        const int mtile = idx >> 16;
        const int g = lane >> 2, tg = lane & 3;

        const int r0 = mtile * 128 + mb * 16 + g;
        const int c0 = kc * 64 + k16 * 16 + tg * 2;
        const float* p = A + (size_t)r0 * N_ + c0;

        const float2 v0 = *reinterpret_cast<const float2*>(p);
        const float2 v1 = *reinterpret_cast<const float2*>(p + 8 * N_);
        const float2 v2 = *reinterpret_cast<const float2*>(p + 8);
        const float2 v3 = *reinterpret_cast<const float2*>(p + 8 * N_ + 8);

        uint4 t;
        t.x = pack_h2(v0.x, v0.y);
        t.y = pack_h2(v1.x, v1.y);
        t.z = pack_h2(v2.x, v2.y);
        t.w = pack_h2(v3.x, v3.y);
        g_Ah[idx] = t;
        return;
    }

    // ---------------- X = Z@W, fragment write ----------------
    const int v = blockIdx.x - 8192;   // 0 .. 1023
    const int kc = v & 63;
    const int b = v >> 6;
    const int m0 = kc * 64;

    for (int i = tid; i < D_ * D_; i += 256) sW[i] = W[i];
    const float4* Zp = reinterpret_cast<const float4*>(Z + ((size_t)b * N_ + m0) * D_);
    for (int f = tid; f < 1024; f += 256) {
        float4 vv = Zp[f];
        int r = f >> 4, c = (f & 15) * 4;
        sZ[r][c] = vv.x; sZ[r][c + 1] = vv.y; sZ[r][c + 2] = vv.z; sZ[r][c + 3] = vv.w;
    }
    __syncthreads();

    const int tx = tid & 15, ty = tid >> 4;
    float acc[4][4] = {};
    #pragma unroll
    for (int d = 0; d < D_; d++) {
        const float4 w = *reinterpret_cast<const float4*>(&sW[d * D_ + tx * 4]);
        #pragma unroll
        for (int i = 0; i < 4; i++) {
            const float z = sZ[ty * 4 + i][d];
            acc[i][0] += z * w.x; acc[i][1] += z * w.y;
            acc[i][2] += z * w.z; acc[i][3] += z * w.w;
        }
    }
    #pragma unroll
    for (int j = 0; j < 4; j++) {
        const uint32_t h0 = pack_h2(acc[0][j], acc[1][j]);
        const uint32_t h1 = pack_h2(acc[2][j], acc[3][j]);
        *reinterpret_cast<uint32_t*>(&sXT[tx * 4 + j][ty * 4])     = h0;
        *reinterpret_cast<uint32_t*>(&sXT[tx * 4 + j][ty * 4 + 2]) = h1;
    }
    __syncthreads();

    // fragment write: 1024 uint2 per block; ntile = b>>1, nb base = (b&1)*8
    const size_t base = (((size_t)(b >> 1) * 64 + kc) * 16 + (b & 1) * 8) * 128;
    #pragma unroll
    for (int it = 0; it < 4; it++) {
        const int f = tid + it * 256;              // nbl*128 + k16*32 + lane
        const int lane = f & 31;
        const int k16 = (f >> 5) & 3;
        const int nbl = f >> 7;
        const int n_local = nbl * 8 + (lane >> 2);
        const int k_local = k16 * 16 + (lane & 3) * 2;
        uint2 t;
        t.x = *reinterpret_cast<const uint32_t*>(&sXT[n_local][k_local]);
        t.y = *reinterpret_cast<const uint32_t*>(&sXT[n_local][k_local + 8]);
        g_Xb[base + f] = t;
    }
}

// ---------------------------------------------------------------------------
// Stage 2: Y = A @ X via mma.sync fp16/f32. CTA 128x128, 4 warps (2m x 2n),
// warp tile 64x64, K-chunk 64, 3-stage cp.async pipeline, 2 CTAs/SM.
// ---------------------------------------------------------------------------
__global__ __launch_bounds__(NTHR, 2)
void gemm_mma_kernel(float* __restrict__ out) {
    extern __shared__ __align__(16) uint4 smem[];
    const int tid = threadIdx.x;
    const int ntile = blockIdx.x;   // 0..7
    const int mtile = blockIdx.y;   // 0..31

    const uint4* Abase = g_Ah + (size_t)mtile * 64 * A_U4;              // [kc][1024 u4]
    const uint4* Bbase = reinterpret_cast<const uint4*>(g_Xb)
                       + (size_t)ntile * 64 * B_U4;                     // [kc][1024 u4]

    auto load_stage = [&](int s, int i) {
        uint4* As4 = smem + s * STAGE_U4;
        uint4* Bs4 = As4 + A_U4;
        const uint4* Ag = Abase + (size_t)i * A_U4;
        const uint4* Bg = Bbase + (size_t)i * B_U4;
        #pragma unroll
        for (int j = 0; j < 8; j++) cp_async16(As4 + tid + j * NTHR, Ag + tid + j * NTHR);
        #pragma unroll
        for (int j = 0; j < 8; j++) cp_async16(Bs4 + tid + j * NTHR, Bg + tid + j * NTHR);
    };

    const int wid = tid >> 5;            // 0..3
    const int lane = tid & 31;
    const int g = lane >> 2;
    const int tg = lane & 3;
    const int mbw = (wid >> 1) * 4;      // mb base 0/4
    const int nbw = (wid & 1) * 8;       // nb base 0/8

    float C[4][8][4] = {};               // [mt][nt][reg] — 128 regs

    load_stage(0, 0); CP_COMMIT();
    load_stage(1, 1); CP_COMMIT();

    for (int i = 0; i < NCHUNK; i++) {
        CP_WAIT1();
        __syncthreads();

        if (i + 2 < NCHUNK) load_stage((i + 2) % STAGES, i + 2);
        CP_COMMIT();

        const int s = i % STAGES;
        const uint4* As4 = smem + s * STAGE_U4;
        const uint2* Bs2 = reinterpret_cast<const uint2*>(As4 + A_U4);

        #pragma unroll
        for (int kk = 0; kk < 4; kk++) {
            uint32_t a[4][4];
            #pragma unroll
            for (int mt = 0; mt < 4; mt++) {
                const uint4 av = As4[((mbw + mt) * 4 + kk) * 32 + lane];
                a[mt][0] = av.x; a[mt][1] = av.y; a[mt][2] = av.z; a[mt][3] = av.w;
            }
            uint32_t b[8][2];
            #pragma unroll
            for (int nt = 0; nt < 8; nt++) {
                const uint2 bv = Bs2[((nbw + nt) * 4 + kk) * 32 + lane];
                b[nt][0] = bv.x; b[nt][1] = bv.y;
            }
            #pragma unroll
            for (int mt = 0; mt < 4; mt++)
                #pragma unroll
                for (int nt = 0; nt < 8; nt++)
                    mma_f16(C[mt][nt], a[mt], b[nt]);
        }
        // next iteration's post-WAIT barrier orders compute(i) before load(i+3)
    }

    // ---- epilogue: scatter C to out[b][n][e] ----
    #pragma unroll
    for (int mt = 0; mt < 4; mt++) {
        const int row0 = mtile * MT + (mbw + mt) * 16 + g;
        #pragma unroll
        for (int nt = 0; nt < 8; nt++) {
            const int col = ntile * NTI + (nbw + nt) * 8 + tg * 2;  // even
            const int bb = col >> 6;
            const int e = col & 63;
            float* p = out + ((size_t)bb * N_ + row0) * D_ + e;
            *reinterpret_cast<float2*>(p) = make_float2(C[mt][nt][0], C[mt][nt][1]);
            *reinterpret_cast<float2*>(p + 8 * D_) = make_float2(C[mt][nt][2], C[mt][nt][3]);
        }
    }
}

// ---------------------------------------------------------------------------
extern "C" void kernel_launch(void* const* d_in, const int* in_sizes, int n_in,
                              void* d_out, int out_size) {
    const float* Z = (const float*)d_in[0];   // [16, 4096, 64]
    const float* A = (const float*)d_in[1];   // [4096, 4096]
    const float* W = (const float*)d_in[2];   // [64, 64]
    float* out = (float*)d_out;               // [16, 4096, 64]

    prep_kernel<<<8192 + 1024, 256>>>(Z, A, W);

    cudaFuncSetAttribute(gemm_mma_kernel,
                         cudaFuncAttributeMaxDynamicSharedMemorySize, SMEM_BYTES);
    gemm_mma_kernel<<<dim3(NCOL / NTI, N_ / MT), NTHR, SMEM_BYTES>>>(out);
}